// round 2
// baseline (speedup 1.0000x reference)
#include <cuda_runtime.h>
#include <cstdint>

#define NB    512
#define NKV   512
#define DIM   256
#define NH    8
#define INNER 512
#define TJ    32
#define NTILE 16
#define KVROW 260            /* padded row stride in floats */
#define KVBUF (TJ*KVROW)     /* 8320 floats per buffer */

// -------- scratch (static device arrays; no allocation) --------
__device__ float g_Q [NB*INNER];     // inp_q @ Wq
__device__ float g_QT[NB*NH*DIM];    // scale * Wk_h @ Q_h  (folded query)
__device__ float g_C [NB*NH*DIM];    // normalized attention-weighted kv
__device__ float g_OP[NB*INNER];     // c @ Wv per head

// ---------------- generic 64x64 tiled GEMM (row-major, optional B^T) ----------------
__global__ void __launch_bounds__(256) gemm64(
    const float* __restrict__ A, const float* __restrict__ B,
    float* __restrict__ C, const float* __restrict__ bias,
    int K, int lda, int ldb, int ldc,
    int aS, int bS, int cS, float alpha, int transB)
{
    __shared__ float As[16][64];
    __shared__ float Bs[16][68];
    A += (size_t)blockIdx.z * aS;
    B += (size_t)blockIdx.z * bS;
    C += (size_t)blockIdx.z * cS;
    int row0 = blockIdx.y * 64, col0 = blockIdx.x * 64;
    int t  = threadIdx.x;
    int tx = t & 15, ty = t >> 4;
    float acc[4][4] = {};
    for (int k0 = 0; k0 < K; k0 += 16) {
        {   // A tile: 64 rows x 16 k
            int i = t >> 2, kf = (t & 3) * 4;
            float4 v = *(const float4*)(A + (size_t)(row0 + i) * lda + k0 + kf);
            As[kf+0][i] = v.x; As[kf+1][i] = v.y;
            As[kf+2][i] = v.z; As[kf+3][i] = v.w;
        }
        if (!transB) {
            int k = t >> 4, j = (t & 15) * 4;
            float4 v = *(const float4*)(B + (size_t)(k0 + k) * ldb + col0 + j);
            Bs[k][j+0] = v.x; Bs[k][j+1] = v.y;
            Bs[k][j+2] = v.z; Bs[k][j+3] = v.w;
        } else {
            int j = t >> 2, kf = (t & 3) * 4;
            float4 v = *(const float4*)(B + (size_t)(col0 + j) * ldb + k0 + kf);
            Bs[kf+0][j] = v.x; Bs[kf+1][j] = v.y;
            Bs[kf+2][j] = v.z; Bs[kf+3][j] = v.w;
        }
        __syncthreads();
#pragma unroll
        for (int k = 0; k < 16; ++k) {
            float4 av = *(const float4*)&As[k][ty*4];
            float4 bv = *(const float4*)&Bs[k][tx*4];
            acc[0][0] += av.x*bv.x; acc[0][1] += av.x*bv.y; acc[0][2] += av.x*bv.z; acc[0][3] += av.x*bv.w;
            acc[1][0] += av.y*bv.x; acc[1][1] += av.y*bv.y; acc[1][2] += av.y*bv.z; acc[1][3] += av.y*bv.w;
            acc[2][0] += av.z*bv.x; acc[2][1] += av.z*bv.y; acc[2][2] += av.z*bv.z; acc[2][3] += av.z*bv.w;
            acc[3][0] += av.w*bv.x; acc[3][1] += av.w*bv.y; acc[3][2] += av.w*bv.z; acc[3][3] += av.w*bv.w;
        }
        __syncthreads();
    }
#pragma unroll
    for (int r = 0; r < 4; ++r) {
        size_t row = (size_t)(row0 + ty*4 + r);
#pragma unroll
        for (int c = 0; c < 4; ++c) {
            int col = col0 + tx*4 + c;
            float v = alpha * acc[r][c];
            if (bias) v += bias[col];
            C[row * ldc + col] = v;
        }
    }
}

// ---------------- fused attention kernel ----------------
__device__ __forceinline__ uint32_t smem_u32(const void* p) {
    return (uint32_t)__cvta_generic_to_shared(p);
}
__device__ __forceinline__ void cpa16(uint32_t d, const void* s) {
    asm volatile("cp.async.cg.shared.global [%0], [%1], 16;" :: "r"(d), "l"(s));
}
__device__ __forceinline__ void cpa_commit() {
    asm volatile("cp.async.commit_group;");
}
__device__ __forceinline__ void cpa_wait0() {
    asm volatile("cp.async.wait_group 0;");
}

// smem layout (floats)
#define QT_OFF   0
#define KV_OFF   2048
#define PART_OFF (KV_OFF + 2*KVBUF)       // 18688, 512 floats
#define DOTS_OFF (PART_OFF + 512)         // 19200, 4096 floats
#define P_OFF    (DOTS_OFF + 4096)        // 23296, 256 floats (layout [j][8])
#define RS_OFF   (P_OFF + 256)            // 8
#define MF_OFF   (RS_OFF + 8)             // 8
#define LF_OFF   (MF_OFF + 8)             // 8
#define HS_OFF   (LF_OFF + 8)             // 512
#define RV_OFF   (HS_OFF + 512)           // 8
#define RI_OFF   (RV_OFF + 8)             // 8
#define SMEM_FLOATS (RI_OFF + 8)
#define SMEM_BYTES  (SMEM_FLOATS * 4)

__global__ void __launch_bounds__(256, 2) attn_main(
    const float* __restrict__ kvg, const int* __restrict__ mask,
    float* __restrict__ cout, float* __restrict__ out, int out_size)
{
    extern __shared__ float sm[];
    const int b    = blockIdx.x;
    const int t    = threadIdx.x;
    const int w    = t >> 5;
    const int lane = t & 31;
    const float* kvb = kvg + (size_t)b * NKV * DIM;

    // load qt for this batch: 2048 floats
    {
        const float4* src = (const float4*)(g_QT + (size_t)b * NH * DIM);
        float4* dst = (float4*)(sm + QT_OFF);
#pragma unroll
        for (int i = 0; i < 2; ++i) dst[t + 256*i] = src[t + 256*i];
    }

    // prologue: prefetch tile 0
    {
        float* dst = sm + KV_OFF;
#pragma unroll
        for (int c = 0; c < 8; ++c) {
            int chunk = t + 256*c;
            int row = chunk >> 6, col4 = chunk & 63;
            cpa16(smem_u32(dst + row*KVROW + col4*4), kvb + row*DIM + col4*4);
        }
        cpa_commit();
    }

    float cacc[NH];
#pragma unroll
    for (int h = 0; h < NH; ++h) cacc[h] = 0.f;
    float mrun = -1e30f, lrun = 0.f;

    const int hp   = (w & 3) * 2;     // head pair for score phase
    const int half = w >> 2;          // m-half: 0 -> [0,128), 1 -> [128,256)

    for (int it = 0; it < NTILE; ++it) {
        const int cur = it & 1;
        const int j0  = it * TJ;
        float* kvt = sm + KV_OFF + cur * KVBUF;

        cpa_wait0();
        __syncthreads();              // tile `cur` visible; prev readers of `nxt` done

        // prefetch next tile into the other buffer
        if (it + 1 < NTILE) {
            float* dst = sm + KV_OFF + (1 - cur) * KVBUF;
            const float* src = kvb + (size_t)(j0 + TJ) * DIM;
#pragma unroll
            for (int c = 0; c < 8; ++c) {
                int chunk = t + 256*c;
                int row = chunk >> 6, col4 = chunk & 63;
                cpa16(smem_u32(dst + row*KVROW + col4*4), src + row*DIM + col4*4);
            }
            cpa_commit();
        }

        // ---- score partials: warp w covers heads {hp, hp+1}, m-half `half`, lane=j ----
        {
            const float4* kr = (const float4*)(kvt + lane * KVROW) + half * 32;
            const float4* qa = (const float4*)(sm + QT_OFF + hp * DIM) + half * 32;
            const float4* qb = qa + 64;   // next head (+256 floats)
            float sa = 0.f, sb = 0.f;
#pragma unroll 8
            for (int m = 0; m < 32; ++m) {
                float4 kv4 = kr[m], a = qa[m], bb = qb[m];
                sa += kv4.x*a.x  + kv4.y*a.y  + kv4.z*a.z  + kv4.w*a.w;
                sb += kv4.x*bb.x + kv4.y*bb.y + kv4.z*bb.z + kv4.w*bb.w;
            }
            sm[PART_OFF + half*256 + hp*32 + lane]     = sa;
            sm[PART_OFF + half*256 + (hp+1)*32 + lane] = sb;
        }
        __syncthreads();

        // ---- warp w = head w: assemble score, mask, online softmax ----
        {
            float s = sm[PART_OFF + w*32 + lane] + sm[PART_OFF + 256 + w*32 + lane];
            int mv = mask[b * NKV + j0 + lane];
            s += -10000.0f * (1.0f - (float)mv);
            sm[DOTS_OFF + w*NKV + j0 + lane] = s;

            float tmax = s;
#pragma unroll
            for (int off = 16; off > 0; off >>= 1)
                tmax = fmaxf(tmax, __shfl_xor_sync(0xffffffffu, tmax, off));
            float mnew = fmaxf(mrun, tmax);
            float p = __expf(s - mnew);
            float ps = p;
#pragma unroll
            for (int off = 16; off > 0; off >>= 1)
                ps += __shfl_xor_sync(0xffffffffu, ps, off);
            float rescale = __expf(mrun - mnew);
            lrun = lrun * rescale + ps;
            mrun = mnew;
            sm[P_OFF + lane * 8 + w] = p;
            if (lane == 0) sm[RS_OFF + w] = rescale;
        }
        __syncthreads();

        // ---- c accumulation: thread t owns column m=t for all 8 heads ----
        {
            float4 r0 = *(const float4*)&sm[RS_OFF];
            float4 r1 = *(const float4*)&sm[RS_OFF + 4];
            cacc[0] *= r0.x; cacc[1] *= r0.y; cacc[2] *= r0.z; cacc[3] *= r0.w;
            cacc[4] *= r1.x; cacc[5] *= r1.y; cacc[6] *= r1.z; cacc[7] *= r1.w;
            const float* kvcol = kvt + t;
#pragma unroll 4
            for (int j = 0; j < TJ; ++j) {
                float kvv = kvcol[j * KVROW];
                float4 pa = *(const float4*)&sm[P_OFF + j*8];
                float4 pb = *(const float4*)&sm[P_OFF + j*8 + 4];
                cacc[0] += pa.x*kvv; cacc[1] += pa.y*kvv;
                cacc[2] += pa.z*kvv; cacc[3] += pa.w*kvv;
                cacc[4] += pb.x*kvv; cacc[5] += pb.y*kvv;
                cacc[6] += pb.z*kvv; cacc[7] += pb.w*kvv;
            }
        }
    }

    // ---- epilogue ----
    if (lane == 0) { sm[MF_OFF + w] = mrun; sm[LF_OFF + w] = lrun; }
    __syncthreads();

    float invl[NH];
#pragma unroll
    for (int h = 0; h < NH; ++h) invl[h] = 1.0f / sm[LF_OFF + h];

    // normalized attention-weighted kv
#pragma unroll
    for (int h = 0; h < NH; ++h)
        cout[(size_t)b * NH * DIM + h * DIM + t] = cacc[h] * invl[h];

    // head_sum
    for (int jj = t; jj < NKV; jj += 256) {
        float sum = 0.f;
#pragma unroll
        for (int h = 0; h < NH; ++h)
            sum += __expf(sm[DOTS_OFF + h*NKV + jj] - sm[MF_OFF + h]) * invl[h];
        sm[HS_OFF + jj] = sum;
    }
    __syncthreads();

    // top-4 (descending value, lowest index tie-break — matches jax.lax.top_k)
    int* redi = (int*)&sm[RI_OFF];
    for (int kk = 0; kk < 4; ++kk) {
        float bv = -3.0f; int bi = 0x7fffffff;
        for (int jj = t; jj < NKV; jj += 256) {
            float v = sm[HS_OFF + jj];
            if (v > bv || (v == bv && jj < bi)) { bv = v; bi = jj; }
        }
#pragma unroll
        for (int off = 16; off > 0; off >>= 1) {
            float ov = __shfl_xor_sync(0xffffffffu, bv, off);
            int   oi = __shfl_xor_sync(0xffffffffu, bi, off);
            if (ov > bv || (ov == bv && oi < bi)) { bv = ov; bi = oi; }
        }
        if (lane == 0) { sm[RV_OFF + w] = bv; redi[w] = bi; }
        __syncthreads();
        if (t == 0) {
            float Bv = sm[RV_OFF]; int Bi = redi[0];
#pragma unroll
            for (int r = 1; r < 8; ++r) {
                float rv = sm[RV_OFF + r]; int ri = redi[r];
                if (rv > Bv || (rv == Bv && ri < Bi)) { Bv = rv; Bi = ri; }
            }
            int oidx = NB * DIM + b * 4 + kk;
            if (oidx < out_size) out[oidx] = (float)Bi;
            sm[HS_OFF + Bi] = -2.0f;  // head_sum >= 0, so this removes it
        }
        __syncthreads();
    }
}

// ---------------- host launcher ----------------
extern "C" void kernel_launch(void* const* d_in, const int* in_sizes, int n_in,
                              void* d_out, int out_size)
{
    const float* inp_q  = (const float*)d_in[0];
    const float* inp_kv = (const float*)d_in[1];
    const int*   maskp  = (const int*)  d_in[2];
    const float* Wq     = (const float*)d_in[3];
    const float* Wk     = (const float*)d_in[4];
    const float* Wv     = (const float*)d_in[5];
    const float* Wo     = (const float*)d_in[6];
    const float* bo     = (const float*)d_in[7];
    float* out = (float*)d_out;

    float *pQ, *pQT, *pC, *pOP;
    cudaGetSymbolAddress((void**)&pQ,  g_Q);
    cudaGetSymbolAddress((void**)&pQT, g_QT);
    cudaGetSymbolAddress((void**)&pC,  g_C);
    cudaGetSymbolAddress((void**)&pOP, g_OP);

    cudaFuncSetAttribute(attn_main, cudaFuncAttributeMaxDynamicSharedMemorySize, SMEM_BYTES);

    const float scale = 0.125f;  // 64^-0.5

    // E1: Q = inp_q @ Wq   (512x256 @ 256x512)
    gemm64<<<dim3(INNER/64, NB/64, 1), 256>>>(
        inp_q, Wq, pQ, nullptr, DIM, DIM, INNER, INNER, 0, 0, 0, 1.0f, 0);

    // E2: qt[b,h,m] = scale * Q[b, h*64:+64] @ Wk[:, h*64:+64]^T   (batched over h)
    gemm64<<<dim3(DIM/64, NB/64, NH), 256>>>(
        pQ, Wk, pQT, nullptr, 64, INNER, INNER, NH*DIM, 64, 64, DIM, scale, 1);

    // E3: fused attention (dots, softmax, weighted-kv, head_sum, top-k)
    attn_main<<<NB, 256, SMEM_BYTES>>>(inp_kv, maskp, pC, out, out_size);

    // E4: op[b, h*64+d] = c[b,h,:] @ Wv[:, h*64:+64]   (batched over h)
    gemm64<<<dim3(1, NB/64, NH), 256>>>(
        pC, Wv, pOP, nullptr, DIM, NH*DIM, INNER, INNER, DIM, 64, 64, 1.0f, 0);

    // E5: out = op @ Wo + bo   (512x512 @ 512x256)
    gemm64<<<dim3(DIM/64, NB/64, 1), 256>>>(
        pOP, Wo, out, bo, INNER, INNER, DIM, DIM, 0, 0, 0, 1.0f, 0);
}

// round 5
// speedup vs baseline: 1.2686x; 1.2686x over previous
#include <cuda_runtime.h>
#include <cstdint>

#define NB    512
#define NKV   512
#define DIM   256
#define NH    8
#define INNER 512
#define TJ    32
#define NTILE 16
#define KVROW 268            /* 268 mod 32 = 12 -> conflict-free float4 row access */
#define KVBUF (TJ*KVROW)     /* 8576 floats per buffer */

// -------- scratch (static device arrays; no allocation) --------
__device__ float g_Q [NB*INNER];     // inp_q @ Wq
__device__ float g_QT[NB*NH*DIM];    // scale * Q_h @ Wk_h^T (folded query)
__device__ float g_C [NB*NH*DIM];    // normalized attention-weighted kv
__device__ float g_OP[NB*INNER];     // c @ Wv per head

// ---------------- 64x64 tiled GEMM, optional split-K via atomicAdd ----------------
template<bool ATOMIC>
__global__ void __launch_bounds__(256) gemm64_t(
    const float* __restrict__ A, const float* __restrict__ B,
    float* __restrict__ C, const float* __restrict__ bias,
    int Kc, int lda, int ldb, int ldc,
    int aS, int bS, int cS, float alpha, int transB, int nSplit)
{
    __shared__ float As[16][64];
    __shared__ float Bs[16][68];
    int z  = blockIdx.z;
    int bz = z / nSplit, kc = z - bz * nSplit;
    A += (size_t)bz * aS + (size_t)kc * Kc;
    if (transB) B += (size_t)bz * bS + (size_t)kc * Kc;
    else        B += (size_t)bz * bS + (size_t)kc * Kc * ldb;
    C += (size_t)bz * cS;

    int row0 = blockIdx.y * 64, col0 = blockIdx.x * 64;
    int t  = threadIdx.x;
    int tx = t & 15, ty = t >> 4;
    float acc[4][4] = {};
    for (int k0 = 0; k0 < Kc; k0 += 16) {
        {   // A tile: 64 rows x 16 k (transposed store)
            int i = t >> 2, kf = (t & 3) * 4;
            float4 v = *(const float4*)(A + (size_t)(row0 + i) * lda + k0 + kf);
            As[kf+0][i] = v.x; As[kf+1][i] = v.y;
            As[kf+2][i] = v.z; As[kf+3][i] = v.w;
        }
        if (!transB) {
            int k = t >> 4, j = (t & 15) * 4;
            float4 v = *(const float4*)(B + (size_t)(k0 + k) * ldb + col0 + j);
            Bs[k][j+0] = v.x; Bs[k][j+1] = v.y;
            Bs[k][j+2] = v.z; Bs[k][j+3] = v.w;
        } else {
            int j = t >> 2, kf = (t & 3) * 4;
            float4 v = *(const float4*)(B + (size_t)(col0 + j) * ldb + k0 + kf);
            Bs[kf+0][j] = v.x; Bs[kf+1][j] = v.y;
            Bs[kf+2][j] = v.z; Bs[kf+3][j] = v.w;
        }
        __syncthreads();
#pragma unroll
        for (int k = 0; k < 16; ++k) {
            float4 av = *(const float4*)&As[k][ty*4];
            float4 bv = *(const float4*)&Bs[k][tx*4];
            acc[0][0] += av.x*bv.x; acc[0][1] += av.x*bv.y; acc[0][2] += av.x*bv.z; acc[0][3] += av.x*bv.w;
            acc[1][0] += av.y*bv.x; acc[1][1] += av.y*bv.y; acc[1][2] += av.y*bv.z; acc[1][3] += av.y*bv.w;
            acc[2][0] += av.z*bv.x; acc[2][1] += av.z*bv.y; acc[2][2] += av.z*bv.z; acc[2][3] += av.z*bv.w;
            acc[3][0] += av.w*bv.x; acc[3][1] += av.w*bv.y; acc[3][2] += av.w*bv.z; acc[3][3] += av.w*bv.w;
        }
        __syncthreads();
    }
#pragma unroll
    for (int r = 0; r < 4; ++r) {
        size_t row = (size_t)(row0 + ty*4 + r);
#pragma unroll
        for (int c = 0; c < 4; ++c) {
            int col = col0 + tx*4 + c;
            float v = alpha * acc[r][c];
            if (ATOMIC) {
                atomicAdd(&C[row * ldc + col], v);
            } else {
                if (bias) v += bias[col];
                C[row * ldc + col] = v;
            }
        }
    }
}

// -------- init kernels --------
__global__ void zero_buf(float* p) { p[blockIdx.x * 256 + threadIdx.x] = 0.f; }
__global__ void init_bias(float* out, const float* __restrict__ bo) {
    int i = blockIdx.x * 256 + threadIdx.x;
    out[i] = bo[i & 255];
}

// ---------------- fused attention kernel ----------------
__device__ __forceinline__ uint32_t smem_u32(const void* p) {
    return (uint32_t)__cvta_generic_to_shared(p);
}
__device__ __forceinline__ void cpa16(uint32_t d, const void* s) {
    asm volatile("cp.async.cg.shared.global [%0], [%1], 16;" :: "r"(d), "l"(s));
}
__device__ __forceinline__ void cpa_commit() { asm volatile("cp.async.commit_group;"); }
__device__ __forceinline__ void cpa_wait0()  { asm volatile("cp.async.wait_group 0;"); }

// smem layout (floats)
#define QT_OFF   0
#define KV_OFF   2048
#define PART_OFF (KV_OFF + 2*KVBUF)       // 19200, 1024 floats [4 quarters][8 heads][32 j]
#define DOTS_OFF (PART_OFF + 1024)        // 20224, 4096 floats
#define P_OFF    (DOTS_OFF + 4096)        // 24320, 256 floats, layout [j][8 heads]
#define RS_OFF   (P_OFF + 256)            // 24576, 8
#define MF_OFF   (RS_OFF + 8)             // 8
#define LF_OFF   (MF_OFF + 8)             // 8
#define HS_OFF   (LF_OFF + 8)             // 512
#define RV_OFF   (HS_OFF + 512)           // 8
#define RI_OFF   (RV_OFF + 8)             // 8
#define SMEM_FLOATS (RI_OFF + 8)
#define SMEM_BYTES  (SMEM_FLOATS * 4)

__global__ void __launch_bounds__(256, 2) attn_main(
    const float* __restrict__ kvg, const int* __restrict__ mask,
    float* __restrict__ cout, float* __restrict__ out, int out_size)
{
    extern __shared__ float sm[];
    const int b    = blockIdx.x;
    const int t    = threadIdx.x;
    const int w    = t >> 5;
    const int lane = t & 31;
    const float* kvb = kvg + (size_t)b * NKV * DIM;

    // load qt for this batch: 2048 floats
    {
        const float4* src = (const float4*)(g_QT + (size_t)b * NH * DIM);
        float4* dst = (float4*)(sm + QT_OFF);
        dst[t] = src[t]; dst[t + 256] = src[t + 256];
    }

    // prologue: prefetch tile 0
    {
        float* dst = sm + KV_OFF;
#pragma unroll
        for (int c = 0; c < 8; ++c) {
            int chunk = t + 256*c;
            int row = chunk >> 6, col4 = chunk & 63;
            cpa16(smem_u32(dst + row*KVROW + col4*4), kvb + row*DIM + col4*4);
        }
        cpa_commit();
    }

    float cacc[NH];
#pragma unroll
    for (int h = 0; h < NH; ++h) cacc[h] = 0.f;
    float mrun = -1e30f, lrun = 0.f;

    const int hb = (w >> 2) * 4;         // head group base for score phase
    const int mq = w & 3;                // m-quarter (64 floats)

    for (int it = 0; it < NTILE; ++it) {
        const int cur = it & 1;
        const int j0  = it * TJ;
        float* kvt = sm + KV_OFF + cur * KVBUF;

        cpa_wait0();
        __syncthreads();

        // prefetch next tile into the other buffer
        if (it + 1 < NTILE) {
            float* dst = sm + KV_OFF + (1 - cur) * KVBUF;
            const float* src = kvb + (size_t)(j0 + TJ) * DIM;
#pragma unroll
            for (int c = 0; c < 8; ++c) {
                int chunk = t + 256*c;
                int row = chunk >> 6, col4 = chunk & 63;
                cpa16(smem_u32(dst + row*KVROW + col4*4), src + row*DIM + col4*4);
            }
            cpa_commit();
        }

        // ---- score partials: warp covers 4 heads [hb..hb+3], m-quarter mq, lane = j ----
        {
            const float4* kr = (const float4*)(kvt + (size_t)lane * KVROW) + mq*16;
            const float4* q0 = (const float4*)(sm + QT_OFF + (hb+0)*DIM) + mq*16;
            const float4* q1 = q0 + 64;
            const float4* q2 = q0 + 128;
            const float4* q3 = q0 + 192;
            float s0 = 0.f, s1 = 0.f, s2 = 0.f, s3 = 0.f;
#pragma unroll
            for (int m = 0; m < 16; ++m) {
                float4 kk = kr[m];
                float4 x;
                x = q0[m]; s0 += kk.x*x.x + kk.y*x.y + kk.z*x.z + kk.w*x.w;
                x = q1[m]; s1 += kk.x*x.x + kk.y*x.y + kk.z*x.z + kk.w*x.w;
                x = q2[m]; s2 += kk.x*x.x + kk.y*x.y + kk.z*x.z + kk.w*x.w;
                x = q3[m]; s3 += kk.x*x.x + kk.y*x.y + kk.z*x.z + kk.w*x.w;
            }
            sm[PART_OFF + mq*256 + (hb+0)*32 + lane] = s0;
            sm[PART_OFF + mq*256 + (hb+1)*32 + lane] = s1;
            sm[PART_OFF + mq*256 + (hb+2)*32 + lane] = s2;
            sm[PART_OFF + mq*256 + (hb+3)*32 + lane] = s3;
        }
        __syncthreads();

        // ---- warp w = head w: assemble score, mask, online softmax ----
        {
            float s = sm[PART_OFF +        w*32 + lane]
                    + sm[PART_OFF + 256  + w*32 + lane]
                    + sm[PART_OFF + 512  + w*32 + lane]
                    + sm[PART_OFF + 768  + w*32 + lane];
            int mv = mask[b * NKV + j0 + lane];
            s += -10000.0f * (1.0f - (float)mv);
            sm[DOTS_OFF + w*NKV + j0 + lane] = s;

            float tmax = s;
#pragma unroll
            for (int off = 16; off > 0; off >>= 1)
                tmax = fmaxf(tmax, __shfl_xor_sync(0xffffffffu, tmax, off));
            float mnew = fmaxf(mrun, tmax);
            float p = __expf(s - mnew);
            float ps = p;
#pragma unroll
            for (int off = 16; off > 0; off >>= 1)
                ps += __shfl_xor_sync(0xffffffffu, ps, off);
            float rescale = __expf(mrun - mnew);
            lrun = lrun * rescale + ps;
            mrun = mnew;
            sm[P_OFF + lane * 8 + w] = p;
            if (lane == 0) sm[RS_OFF + w] = rescale;
        }
        __syncthreads();

        // ---- c accumulation: thread t owns column m=t for all 8 heads ----
        {
            float4 r0 = *(const float4*)&sm[RS_OFF];
            float4 r1 = *(const float4*)&sm[RS_OFF + 4];
            cacc[0] *= r0.x; cacc[1] *= r0.y; cacc[2] *= r0.z; cacc[3] *= r0.w;
            cacc[4] *= r1.x; cacc[5] *= r1.y; cacc[6] *= r1.z; cacc[7] *= r1.w;
            const float* kvcol = kvt + t;
#pragma unroll 8
            for (int j = 0; j < TJ; ++j) {
                float kvv = kvcol[(size_t)j * KVROW];
                float4 pa = *(const float4*)&sm[P_OFF + j*8];
                float4 pb = *(const float4*)&sm[P_OFF + j*8 + 4];
                cacc[0] += pa.x*kvv; cacc[1] += pa.y*kvv;
                cacc[2] += pa.z*kvv; cacc[3] += pa.w*kvv;
                cacc[4] += pb.x*kvv; cacc[5] += pb.y*kvv;
                cacc[6] += pb.z*kvv; cacc[7] += pb.w*kvv;
            }
        }
    }

    // ---- epilogue ----
    if (lane == 0) { sm[MF_OFF + w] = mrun; sm[LF_OFF + w] = lrun; }
    __syncthreads();

    float invl[NH];
#pragma unroll
    for (int h = 0; h < NH; ++h) invl[h] = 1.0f / sm[LF_OFF + h];

    // normalized attention-weighted kv
#pragma unroll
    for (int h = 0; h < NH; ++h)
        cout[(size_t)b * NH * DIM + h * DIM + t] = cacc[h] * invl[h];

    // head_sum
    for (int jj = t; jj < NKV; jj += 256) {
        float sum = 0.f;
#pragma unroll
        for (int h = 0; h < NH; ++h)
            sum += __expf(sm[DOTS_OFF + h*NKV + jj] - sm[MF_OFF + h]) * invl[h];
        sm[HS_OFF + jj] = sum;
    }
    __syncthreads();

    // top-4 (descending value, lowest index tie-break — matches jax.lax.top_k)
    int* redi = (int*)&sm[RI_OFF];
    for (int kk = 0; kk < 4; ++kk) {
        float bv = -3.0f; int bi = 0x7fffffff;
        for (int jj = t; jj < NKV; jj += 256) {
            float v = sm[HS_OFF + jj];
            if (v > bv || (v == bv && jj < bi)) { bv = v; bi = jj; }
        }
#pragma unroll
        for (int off = 16; off > 0; off >>= 1) {
            float ov = __shfl_xor_sync(0xffffffffu, bv, off);
            int   oi = __shfl_xor_sync(0xffffffffu, bi, off);
            if (ov > bv || (ov == bv && oi < bi)) { bv = ov; bi = oi; }
        }
        if (lane == 0) { sm[RV_OFF + w] = bv; redi[w] = bi; }
        __syncthreads();
        if (t == 0) {
            float Bv = sm[RV_OFF]; int Bi = redi[0];
#pragma unroll
            for (int r = 1; r < 8; ++r) {
                float rv = sm[RV_OFF + r]; int ri = redi[r];
                if (rv > Bv || (rv == Bv && ri < Bi)) { Bv = rv; Bi = ri; }
            }
            int oidx = NB * DIM + b * 4 + kk;
            if (oidx < out_size) out[oidx] = (float)Bi;
            sm[HS_OFF + Bi] = -2.0f;  // head_sum >= 0, so this removes it
        }
        __syncthreads();
    }
}

// ---------------- host launcher ----------------
extern "C" void kernel_launch(void* const* d_in, const int* in_sizes, int n_in,
                              void* d_out, int out_size)
{
    const float* inp_q  = (const float*)d_in[0];
    const float* inp_kv = (const float*)d_in[1];
    const int*   maskp  = (const int*)  d_in[2];
    const float* Wq     = (const float*)d_in[3];
    const float* Wk     = (const float*)d_in[4];
    const float* Wv     = (const float*)d_in[5];
    const float* Wo     = (const float*)d_in[6];
    const float* bo     = (const float*)d_in[7];
    float* out = (float*)d_out;

    float *pQ, *pQT, *pC, *pOP;
    cudaGetSymbolAddress((void**)&pQ,  g_Q);
    cudaGetSymbolAddress((void**)&pQT, g_QT);
    cudaGetSymbolAddress((void**)&pC,  g_C);
    cudaGetSymbolAddress((void**)&pOP, g_OP);

    cudaFuncSetAttribute(attn_main, cudaFuncAttributeMaxDynamicSharedMemorySize, SMEM_BYTES);

    const float scale = 0.125f;  // 64^-0.5

    // zero-init for split-K atomic targets
    zero_buf<<<1024, 256>>>(pQ);

    // E1: Q = inp_q @ Wq   (512x256 @ 256x512), split-K=4 -> 256 CTAs
    gemm64_t<true><<<dim3(INNER/64, NB/64, 4), 256>>>(
        inp_q, Wq, pQ, nullptr, 64, DIM, INNER, INNER, 0, 0, 0, 1.0f, 0, 4);

    // E2: qt[b,h,m] = scale * Q_h @ Wk_h^T  (batched over h, K=64) -> 256 CTAs
    gemm64_t<false><<<dim3(DIM/64, NB/64, NH), 256>>>(
        pQ, Wk, pQT, nullptr, 64, INNER, INNER, NH*DIM, 64, 64, DIM, scale, 1, 1);

    // E3: fused attention (dots, softmax, weighted-kv, head_sum, top-k)
    attn_main<<<NB, 256, SMEM_BYTES>>>(inp_kv, maskp, pC, out, out_size);

    // zero-init op, bias-init out (topk region written by attn is untouched)
    zero_buf<<<1024, 256>>>(pOP);
    init_bias<<<512, 256>>>(out, bo);

    // E4: op_h = c_h @ Wv_h  (batched over h, split-K=2) -> 128 CTAs
    gemm64_t<true><<<dim3(1, NB/64, NH*2), 256>>>(
        pC, Wv, pOP, nullptr, 128, NH*DIM, INNER, INNER, DIM, 64, 64, 1.0f, 0, 2);

    // E5: out += op @ Wo  (512x512 @ 512x256), split-K=4 -> 128 CTAs
    gemm64_t<true><<<dim3(DIM/64, NB/64, 4), 256>>>(
        pOP, Wo, out, nullptr, 128, INNER, DIM, DIM, 0, 0, 0, 1.0f, 0, 4);
}